// round 1
// baseline (speedup 1.0000x reference)
#include <cuda_runtime.h>

#define Bn 8
#define Hn 192
#define Wn 192
#define Sn 4
#define Cn 32

// Scratch: stage1 max (8,228,264,32)=15,409,152 ; stage2 max (8,228,228,32)=13,307,904
__device__ float g_c1[15409152];
__device__ float g_o1[15409152];
__device__ float g_c2[13307904];
__device__ float g_o2[13307904];

// STAGE: 1 = H-axis from x (clamped edge pad), dilate(c-chain)/erode(o-chain) with k
//        2 = W-axis, same ops, from scratch
//        3 = H-axis, erode(c)/dilate(o) with k*c
//        4 = W-axis, erode(c)/dilate(o) with k*c, alpha-blend, write final slice
template<int WID, int STAGE, int BH>
__global__ __launch_bounds__(256)
void morph_kernel(const float* __restrict__ inC, const float* __restrict__ inO,
                  float* __restrict__ outC, float* __restrict__ outO,
                  const float* __restrict__ x,
                  const float* __restrict__ coef,
                  const float* __restrict__ cmul,
                  const float* __restrict__ alpha,
                  float* __restrict__ out_final,
                  int OH, int OW, int IH, int IW,
                  int scale_idx, float inv_s2)
{
    constexpr int L = 2 * WID + 1;
    constexpr bool AXIS_W = (STAGE == 2 || STAGE == 4);
    constexpr bool SECOND = (STAGE >= 3);

    const int lane = threadIdx.x & 31;
    const int warp = threadIdx.x >> 5;
    const int b    = blockIdx.z;
    const int line = blockIdx.y * 8 + warp;
    const int a0   = blockIdx.x * BH;

    const int nlines = AXIS_W ? OH : OW;
    if (line >= nlines) return;

    float a = coef[lane] * inv_s2;
    if (SECOND) a *= cmul[lane];

    const float PINF = __int_as_float(0x7f800000);
    float vc[BH], vo[BH];
#pragma unroll
    for (int p = 0; p < BH; ++p) {
        vc[p] = SECOND ? PINF : -PINF;
        vo[p] = SECOND ? -PINF : PINF;
    }

    const float* pC = nullptr;
    const float* pO = nullptr;
    int strideM = 0;
    if constexpr (STAGE == 1) {
        // virtual edge padding of 2*WID; line is padded-w coordinate
        int xw = min(max(line - 2 * WID, 0), Wn - 1);
        pC = x + (b * Hn * Wn + xw) * (Sn * Cn) + scale_idx * Cn + lane;
    } else if constexpr (!AXIS_W) {
        pC = inC + (b * IH * IW + line) * Cn + lane;
        pO = inO + (b * IH * IW + line) * Cn + lane;
        strideM = IW * Cn;
    } else {
        pC = inC + ((b * IH + line) * IW) * Cn + lane;
        pO = inO + ((b * IH + line) * IW) * Cn + lane;
        strideM = Cn;
    }

#pragma unroll
    for (int m = 0; m < BH + L - 1; ++m) {
        float xc, xo;
        if constexpr (STAGE == 1) {
            int xh = min(max(a0 + m - 2 * WID, 0), Hn - 1);
            xc = __ldg(pC + xh * (Wn * Sn * Cn));
            xo = xc;
        } else {
            int lim = (AXIS_W ? IW : IH) - 1;
            int im = min(a0 + m, lim);
            xc = __ldg(pC + im * strideM);
            xo = __ldg(pO + im * strideM);
        }
#pragma unroll
        for (int p = 0; p < BH; ++p) {
            int j = m - p;
            if (j < 0 || j >= L) continue;
            float dj2 = (float)((j - WID) * (j - WID));
            if (!SECOND) {
                vc[p] = fmaxf(vc[p], fmaf(-dj2, a, xc));
                vo[p] = fminf(vo[p], fmaf( dj2, a, xo));
            } else {
                vc[p] = fminf(vc[p], fmaf( dj2, a, xc));
                vo[p] = fmaxf(vo[p], fmaf(-dj2, a, xo));
            }
        }
    }

    if constexpr (STAGE == 4) {
        float al = alpha[lane];
#pragma unroll
        for (int p = 0; p < BH; ++p) {
            int ow = a0 + p;
            if (ow >= OW) continue;
            float r = fmaf(al, vc[p] - vo[p], vo[p]);  // alpha*xc + (1-alpha)*xo
            out_final[(((b * Hn + line) * Wn + ow) * Sn + scale_idx) * Cn + lane] = r;
        }
    } else if constexpr (!AXIS_W) {
        int base = (b * OH * OW + line) * Cn + lane;
#pragma unroll
        for (int p = 0; p < BH; ++p) {
            int oh = a0 + p;
            if (oh >= OH) continue;
            outC[base + oh * OW * Cn] = vc[p];
            outO[base + oh * OW * Cn] = vo[p];
        }
    } else {
        int base = ((b * OH + line) * OW) * Cn + lane;
#pragma unroll
        for (int p = 0; p < BH; ++p) {
            int ow = a0 + p;
            if (ow >= OW) continue;
            outC[base + ow * Cn] = vc[p];
            outO[base + ow * Cn] = vo[p];
        }
    }
}

static inline int cdiv(int a, int b) { return (a + b - 1) / b; }

template<int WID>
static void run_scale(const float* x, const float* coef, const float* cmul,
                      const float* alpha, float* out, int si, float sf,
                      float* c1, float* o1, float* c2, float* o2)
{
    constexpr int BH = (WID >= 18) ? 12 : 16;
    const float inv_s2 = 1.0f / (sf * sf);

    const int OH1 = Hn + 2 * WID, OW1 = Wn + 4 * WID;   // after H pass 1
    const int OH2 = OH1,          OW2 = Wn + 2 * WID;   // after W pass 1
    const int OH3 = Hn,           OW3 = OW2;            // after H pass 2
    const int OH4 = Hn,           OW4 = Wn;             // final

    {   // stage 1: axis H, input = x with virtual edge pad (IH = Hn + 4*WID)
        dim3 g(cdiv(OH1, BH), cdiv(OW1, 8), Bn);
        morph_kernel<WID, 1, BH><<<g, 256>>>(nullptr, nullptr, c1, o1, x,
                                             coef, cmul, alpha, nullptr,
                                             OH1, OW1, Hn + 4 * WID, OW1, si, inv_s2);
    }
    {   // stage 2: axis W
        dim3 g(cdiv(OW2, BH), cdiv(OH2, 8), Bn);
        morph_kernel<WID, 2, BH><<<g, 256>>>(c1, o1, c2, o2, nullptr,
                                             coef, cmul, alpha, nullptr,
                                             OH2, OW2, OH1, OW1, si, inv_s2);
    }
    {   // stage 3: axis H, taps k*c, swapped ops
        dim3 g(cdiv(OH3, BH), cdiv(OW3, 8), Bn);
        morph_kernel<WID, 3, BH><<<g, 256>>>(c2, o2, c1, o1, nullptr,
                                             coef, cmul, alpha, nullptr,
                                             OH3, OW3, OH2, OW2, si, inv_s2);
    }
    {   // stage 4: axis W, blend + final store
        dim3 g(cdiv(OW4, BH), cdiv(OH4, 8), Bn);
        morph_kernel<WID, 4, BH><<<g, 256>>>(c1, o1, nullptr, nullptr, nullptr,
                                             coef, cmul, alpha, out,
                                             OH4, OW4, OH3, OW3, si, inv_s2);
    }
}

extern "C" void kernel_launch(void* const* d_in, const int* in_sizes, int n_in,
                              void* d_out, int out_size)
{
    const float* x    = (const float*)d_in[0];
    const float* coef = (const float*)d_in[1];
    const float* cm   = (const float*)d_in[2];
    const float* al   = (const float*)d_in[3];
    float* out = (float*)d_out;

    float *c1, *o1, *c2, *o2;
    cudaGetSymbolAddress((void**)&c1, g_c1);
    cudaGetSymbolAddress((void**)&o1, g_o1);
    cudaGetSymbolAddress((void**)&c2, g_c2);
    cudaGetSymbolAddress((void**)&o2, g_o2);

    // scales = (2^i - 1) * 0.25 for i=1..4 ; widths = int(5*s)
    run_scale<1> (x, coef, cm, al, out, 0, 0.25f, c1, o1, c2, o2);
    run_scale<3> (x, coef, cm, al, out, 1, 0.75f, c1, o1, c2, o2);
    run_scale<8> (x, coef, cm, al, out, 2, 1.75f, c1, o1, c2, o2);
    run_scale<18>(x, coef, cm, al, out, 3, 3.75f, c1, o1, c2, o2);
}

// round 2
// speedup vs baseline: 1.2259x; 1.2259x over previous
#include <cuda_runtime.h>

#define Bn 8
#define Hn 192
#define Wn 192
#define Sn 4
#define Cn 32

// Scratch (static, zero-init). Max use: stage1 w=18: 8*228*264*32 = 15,409,152 floats.
// +512K floats slack so unclamped tap loads of discarded outputs stay in-bounds.
__device__ float g_c1[15409152 + 524288];
__device__ float g_o1[15409152 + 524288];
__device__ float g_c2[13307904 + 524288];
__device__ float g_o2[13307904 + 524288];

template<int WID> struct SP;
template<> struct SP<1>  { static constexpr int SI = 0; static constexpr float INVS2 = 16.0f; };
template<> struct SP<3>  { static constexpr int SI = 1; static constexpr float INVS2 = 1.77777778f; };
template<> struct SP<8>  { static constexpr int SI = 2; static constexpr float INVS2 = 0.326530612f; };
template<> struct SP<18> { static constexpr int SI = 3; static constexpr float INVS2 = 0.0711111111f; };

// STAGE 1: H-axis dilate(c)/erode(o) with k, input x w/ virtual edge pad
// STAGE 2: W-axis dilate(c)/erode(o) with k
// STAGE 3: H-axis erode(c)/dilate(o) with k*c
// STAGE 4: W-axis erode(c)/dilate(o) with k*c, alpha-blend, final store
template<int WID, int STAGE, int BH>
__global__ __launch_bounds__(256)
void morph(const float* __restrict__ inC, const float* __restrict__ inO,
           float* __restrict__ outC, float* __restrict__ outO,
           const float* __restrict__ x,
           const float* __restrict__ coef, const float* __restrict__ cmul,
           const float* __restrict__ alpha, float* __restrict__ outF, int b0)
{
    constexpr int L   = 2 * WID + 1;
    constexpr bool AXW    = (STAGE == 2 || STAGE == 4);
    constexpr bool SECOND = (STAGE >= 3);
    constexpr int IH = (STAGE == 2 || STAGE == 3) ? (Hn + 2 * WID) : Hn;
    constexpr int IW = (STAGE == 2) ? (Wn + 4 * WID) : (Wn + 2 * WID);
    constexpr int OH = (STAGE <= 2) ? (Hn + 2 * WID) : Hn;
    constexpr int OW = (STAGE == 1) ? (Wn + 4 * WID)
                     : (STAGE == 4) ? Wn : (Wn + 2 * WID);
    constexpr int NM   = AXW ? OW : OH;      // outputs along morph axis
    constexpr int NL   = AXW ? OH : OW;      // independent lines
    constexpr int MSTR = AXW ? Cn : IW * Cn; // input stride along morph axis

    const int lane = threadIdx.x & 31;
    const int warp = threadIdx.x >> 5;
    const int b    = b0 + blockIdx.z;
    const int line = blockIdx.y * 8 + warp;
    const int a0   = blockIdx.x * BH;
    if (line >= NL) return;

    float a = coef[lane] * SP<WID>::INVS2;
    if (SECOND) a *= cmul[lane];

    const float PINF = __int_as_float(0x7f800000);
    float vc[BH], vo[BH];
#pragma unroll
    for (int p = 0; p < BH; ++p) {
        vc[p] = SECOND ?  PINF : -PINF;
        vo[p] = SECOND ? -PINF :  PINF;
    }

    if constexpr (STAGE == 1) {
        const int xw = min(max(line - 2 * WID, 0), Wn - 1);
        const float* px = x + (b * Hn * Wn + xw) * (Sn * Cn) + SP<WID>::SI * Cn + lane;
#pragma unroll
        for (int m = 0; m < BH + L - 1; ++m) {
            int xh = min(max(a0 + m - 2 * WID, 0), Hn - 1);
            float v = __ldg(px + xh * (Wn * Sn * Cn));
#pragma unroll
            for (int p = 0; p < BH; ++p) {
                int j = m - p;
                if (j < 0 || j >= L) continue;
                float dj2 = (float)((j - WID) * (j - WID));
                vc[p] = fmaxf(vc[p], fmaf(-dj2, a, v));
                vo[p] = fminf(vo[p], fmaf( dj2, a, v));
            }
        }
    } else {
        const int off = b * (IH * IW) + (AXW ? (line * IW + a0) : (a0 * IW + line));
        const float* pc = inC + off * Cn + lane;
        const float* po = inO + off * Cn + lane;
#pragma unroll
        for (int m = 0; m < BH + L - 1; ++m) {
            float xc = __ldg(pc + m * MSTR);
            float xo = __ldg(po + m * MSTR);
#pragma unroll
            for (int p = 0; p < BH; ++p) {
                int j = m - p;
                if (j < 0 || j >= L) continue;
                float dj2 = (float)((j - WID) * (j - WID));
                if (!SECOND) {
                    vc[p] = fmaxf(vc[p], fmaf(-dj2, a, xc));
                    vo[p] = fminf(vo[p], fmaf( dj2, a, xo));
                } else {
                    vc[p] = fminf(vc[p], fmaf( dj2, a, xc));
                    vo[p] = fmaxf(vo[p], fmaf(-dj2, a, xo));
                }
            }
        }
    }

    if constexpr (STAGE == 4) {
        float al = alpha[lane];
#pragma unroll
        for (int p = 0; p < BH; ++p) {
            int ow = a0 + p;
            if (ow >= OW) continue;
            float r = fmaf(al, vc[p] - vo[p], vo[p]); // alpha*xc + (1-alpha)*xo
            outF[(((b * Hn + line) * Wn + ow) * Sn + SP<WID>::SI) * Cn + lane] = r;
        }
    } else if constexpr (!AXW) {
        int base = (b * OH * OW + line) * Cn + lane;
#pragma unroll
        for (int p = 0; p < BH; ++p) {
            int oh = a0 + p;
            if (oh >= OH) continue;
            outC[base + oh * (OW * Cn)] = vc[p];
            outO[base + oh * (OW * Cn)] = vo[p];
        }
    } else {
        int base = (b * OH + line) * (IW == 0 ? 0 : OW) * Cn + a0 * Cn + lane;
#pragma unroll
        for (int p = 0; p < BH; ++p) {
            int ow = a0 + p;
            if (ow >= OW) continue;
            outC[base + p * Cn] = vc[p];
            outO[base + p * Cn] = vo[p];
        }
    }
}

static inline int cdiv(int a, int b) { return (a + b - 1) / b; }

template<int WID>
static void run_scale(const float* x, const float* coef, const float* cm,
                      const float* al, float* out,
                      float* c1, float* o1, float* c2, float* o2,
                      int b0, int nb)
{
    constexpr int BH = (WID >= 18) ? 12 : 16;
    constexpr int NM1 = Hn + 2 * WID, NL1 = Wn + 4 * WID;
    constexpr int NM2 = Wn + 2 * WID, NL2 = Hn + 2 * WID;
    constexpr int NM3 = Hn,           NL3 = Wn + 2 * WID;
    constexpr int NM4 = Wn,           NL4 = Hn;

    morph<WID, 1, BH><<<dim3(cdiv(NM1, BH), cdiv(NL1, 8), nb), 256>>>(
        nullptr, nullptr, c1, o1, x, coef, cm, al, nullptr, b0);
    morph<WID, 2, BH><<<dim3(cdiv(NM2, BH), cdiv(NL2, 8), nb), 256>>>(
        c1, o1, c2, o2, nullptr, coef, cm, al, nullptr, b0);
    morph<WID, 3, BH><<<dim3(cdiv(NM3, BH), cdiv(NL3, 8), nb), 256>>>(
        c2, o2, c1, o1, nullptr, coef, cm, al, nullptr, b0);
    morph<WID, 4, BH><<<dim3(cdiv(NM4, BH), cdiv(NL4, 8), nb), 256>>>(
        c1, o1, nullptr, nullptr, nullptr, coef, cm, al, out, b0);
}

extern "C" void kernel_launch(void* const* d_in, const int* in_sizes, int n_in,
                              void* d_out, int out_size)
{
    const float* x    = (const float*)d_in[0];
    const float* coef = (const float*)d_in[1];
    const float* cm   = (const float*)d_in[2];
    const float* al   = (const float*)d_in[3];
    float* out = (float*)d_out;

    float *c1, *o1, *c2, *o2;
    cudaGetSymbolAddress((void**)&c1, g_c1);
    cudaGetSymbolAddress((void**)&o1, g_o1);
    cudaGetSymbolAddress((void**)&c2, g_c2);
    cudaGetSymbolAddress((void**)&o2, g_o2);

    // Batch-split G=2: all 4 stages of one (scale, batch-half) complete while
    // its scratch (~57-115 MB) is L2-resident.
    for (int b0 = 0; b0 < Bn; b0 += 4) {
        run_scale<1> (x, coef, cm, al, out, c1, o1, c2, o2, b0, 4);
        run_scale<3> (x, coef, cm, al, out, c1, o1, c2, o2, b0, 4);
        run_scale<8> (x, coef, cm, al, out, c1, o1, c2, o2, b0, 4);
        run_scale<18>(x, coef, cm, al, out, c1, o1, c2, o2, b0, 4);
    }
}

// round 3
// speedup vs baseline: 1.5211x; 1.2408x over previous
#include <cuda_runtime.h>
#include <cuda_fp16.h>

#define Bn 8
#define Hn 192
#define Wn 192
#define Sn 4
#define Cn 32

// Packed scratch: one __half2 = (c_chain, o_chain) per element.
// g1 max extent (w=18): 8*228*264*32 = 15,409,152 elems; g2: 8*228*228*32 = 13,307,904.
__device__ __half2 g_1[15409152 + 524288];
__device__ __half2 g_2[13307904 + 524288];

template<int WID> struct SP;
template<> struct SP<1>  { static constexpr int SI = 0; static constexpr float INVS2 = 16.0f; };
template<> struct SP<3>  { static constexpr int SI = 1; static constexpr float INVS2 = 1.77777778f; };
template<> struct SP<8>  { static constexpr int SI = 2; static constexpr float INVS2 = 0.326530612f; };
template<> struct SP<18> { static constexpr int SI = 3; static constexpr float INVS2 = 0.0711111111f; };

// STAGE 1: H-axis dilate(c)/erode(o), k, input x (virtual edge pad 2w)
// STAGE 2: W-axis dilate(c)/erode(o), k
// STAGE 3: H-axis erode(c)/dilate(o), k*c
// STAGE 4: W-axis erode(c)/dilate(o), k*c, alpha-blend, final store
template<int WID, int STAGE, int BH>
__global__ __launch_bounds__(256)
void morph(const __half2* __restrict__ in, __half2* __restrict__ out,
           const float* __restrict__ x,
           const float* __restrict__ coef, const float* __restrict__ cmul,
           const float* __restrict__ alpha, float* __restrict__ outF)
{
    constexpr int  L      = 2 * WID + 1;
    constexpr bool AXW    = (STAGE == 2 || STAGE == 4);
    constexpr bool SECOND = (STAGE >= 3);
    // input extents (rows IH x cols IW) of scratch, and output extents
    constexpr int IH = (STAGE == 2) ? (Hn + 2 * WID) : (STAGE == 3) ? (Hn + 2 * WID) : Hn;
    constexpr int IW = (STAGE == 2) ? (Wn + 4 * WID) : (Wn + 2 * WID);
    constexpr int OH = (STAGE <= 2) ? (Hn + 2 * WID) : Hn;
    constexpr int OW = (STAGE == 1) ? (Wn + 4 * WID) : (STAGE == 4) ? Wn : (Wn + 2 * WID);
    constexpr int NM = AXW ? OW : OH;   // outputs along morph axis
    constexpr int NL = AXW ? OH : OW;   // independent lines

    const int lane = threadIdx.x & 31;
    const int warp = threadIdx.x >> 5;
    const int b    = blockIdx.z;
    const int line = blockIdx.y * 8 + warp;
    const int a0   = blockIdx.x * BH;
    if (line >= NL) return;

    float a = coef[lane] * SP<WID>::INVS2;
    if (SECOND) a *= cmul[lane];

    const float PINF = __int_as_float(0x7f800000);
    float vc[BH], vo[BH];
#pragma unroll
    for (int p = 0; p < BH; ++p) {
        vc[p] = SECOND ?  PINF : -PINF;
        vo[p] = SECOND ? -PINF :  PINF;
    }

    auto taps1 = [&](float v, int m) {   // stage 1: c=dilate, o=erode, same input
#pragma unroll
        for (int p = 0; p < BH; ++p) {
            int j = m - p;
            if (j < 0 || j >= L) continue;
            float dj2 = (float)((j - WID) * (j - WID));
            vc[p] = fmaxf(vc[p], fmaf(-dj2, a, v));
            vo[p] = fminf(vo[p], fmaf( dj2, a, v));
        }
    };
    auto taps = [&](float xc, float xo, int m) {
#pragma unroll
        for (int p = 0; p < BH; ++p) {
            int j = m - p;
            if (j < 0 || j >= L) continue;
            float dj2 = (float)((j - WID) * (j - WID));
            if (!SECOND) {
                vc[p] = fmaxf(vc[p], fmaf(-dj2, a, xc));
                vo[p] = fminf(vo[p], fmaf( dj2, a, xo));
            } else {
                vc[p] = fminf(vc[p], fmaf( dj2, a, xc));
                vo[p] = fmaxf(vo[p], fmaf(-dj2, a, xo));
            }
        }
    };

    if constexpr (STAGE == 1) {
        const int xw = min(max(line - 2 * WID, 0), Wn - 1);
        const float* px = x + ((b * Hn * Wn + xw) * Sn + SP<WID>::SI) * Cn + lane;
        constexpr int RS = Wn * Sn * Cn;
        const bool interior = (a0 >= 2 * WID) && (a0 + BH + L - 2 <= Hn - 1 + 2 * WID);
        if (interior) {
            const float* p0 = px + (a0 - 2 * WID) * RS;
#pragma unroll
            for (int m = 0; m < BH + L - 1; ++m) taps1(__ldg(p0 + m * RS), m);
        } else {
#pragma unroll
            for (int m = 0; m < BH + L - 1; ++m) {
                int xh = min(max(a0 + m - 2 * WID, 0), Hn - 1);
                taps1(__ldg(px + xh * RS), m);
            }
        }
    } else {
        constexpr int MSTR = AXW ? Cn : IW * Cn;
        const int off = AXW ? ((b * IH + line) * IW + a0)
                            : ((b * IH + a0) * IW + line);
        const __half2* p0 = in + off * Cn + lane;
#pragma unroll
        for (int m = 0; m < BH + L - 1; ++m) {
            float2 f = __half22float2(__ldg(p0 + m * MSTR));
            taps(f.x, f.y, m);
        }
    }

    if constexpr (STAGE == 4) {
        float al = alpha[lane];
#pragma unroll
        for (int p = 0; p < BH; ++p) {
            int ow = a0 + p;
            if (ow >= OW) continue;
            float r = fmaf(al, vc[p] - vo[p], vo[p]); // alpha*xc + (1-alpha)*xo
            outF[(((b * Hn + line) * Wn + ow) * Sn + SP<WID>::SI) * Cn + lane] = r;
        }
    } else if constexpr (!AXW) {   // stage 1/3: outputs along H, line = w
        const int base = (b * OH + a0) * (OW * Cn) + line * Cn + lane;
#pragma unroll
        for (int p = 0; p < BH; ++p) {
            int oh = a0 + p;
            if (oh >= OH) continue;
            out[base + p * (OW * Cn)] = __floats2half2_rn(vc[p], vo[p]);
        }
    } else {                        // stage 2: outputs along W, line = h
        const int base = ((b * OH + line) * OW + a0) * Cn + lane;
#pragma unroll
        for (int p = 0; p < BH; ++p) {
            int ow = a0 + p;
            if (ow >= OW) continue;
            out[base + p * Cn] = __floats2half2_rn(vc[p], vo[p]);
        }
    }
}

static inline int cdiv(int a, int b) { return (a + b - 1) / b; }

template<int WID>
static void run_scale(const float* x, const float* coef, const float* cm,
                      const float* al, float* out, __half2* g1, __half2* g2)
{
    constexpr int BH = (WID >= 18) ? 12 : 16;
    constexpr int NM1 = Hn + 2 * WID, NL1 = Wn + 4 * WID;
    constexpr int NM2 = Wn + 2 * WID, NL2 = Hn + 2 * WID;
    constexpr int NM3 = Hn,           NL3 = Wn + 2 * WID;
    constexpr int NM4 = Wn,           NL4 = Hn;

    morph<WID, 1, BH><<<dim3(cdiv(NM1, BH), cdiv(NL1, 8), Bn), 256>>>(
        nullptr, g1, x, coef, cm, al, nullptr);
    morph<WID, 2, BH><<<dim3(cdiv(NM2, BH), cdiv(NL2, 8), Bn), 256>>>(
        g1, g2, nullptr, coef, cm, al, nullptr);
    morph<WID, 3, BH><<<dim3(cdiv(NM3, BH), cdiv(NL3, 8), Bn), 256>>>(
        g2, g1, nullptr, coef, cm, al, nullptr);
    morph<WID, 4, BH><<<dim3(cdiv(NM4, BH), cdiv(NL4, 8), Bn), 256>>>(
        g1, nullptr, nullptr, coef, cm, al, out);
}

extern "C" void kernel_launch(void* const* d_in, const int* in_sizes, int n_in,
                              void* d_out, int out_size)
{
    const float* x    = (const float*)d_in[0];
    const float* coef = (const float*)d_in[1];
    const float* cm   = (const float*)d_in[2];
    const float* al   = (const float*)d_in[3];
    float* out = (float*)d_out;

    __half2 *g1, *g2;
    cudaGetSymbolAddress((void**)&g1, g_1);
    cudaGetSymbolAddress((void**)&g2, g_2);

    // Full batch per scale: packed half2 scratch keeps live set (<=115 MB) L2-resident.
    run_scale<1> (x, coef, cm, al, out, g1, g2);
    run_scale<3> (x, coef, cm, al, out, g1, g2);
    run_scale<8> (x, coef, cm, al, out, g1, g2);
    run_scale<18>(x, coef, cm, al, out, g1, g2);
}

// round 4
// speedup vs baseline: 1.6406x; 1.0786x over previous
#include <cuda_runtime.h>
#include <cuda_fp16.h>

#define Bn 8
#define Hn 192
#define Wn 192
#define Sn 4
#define Cn 32

// Stream-A scratch (w=18, w=8). Stream-B scratch (w=3, w=1).
// A1: (Hn+36)*Wn*Cn*Bn = 228*192*256 = 11,206,656 ; A2: 228*228*256 = 13,307,904
// B1: 198*192*256 = 9,732,096 ; B2: 198*198*256 = 10,036,224
__device__ __half2 g_A1[11206656 + 262144];
__device__ __half2 g_A2[13307904 + 262144];
__device__ __half2 g_B1[ 9732096 + 262144];
__device__ __half2 g_B2[10036224 + 262144];

template<int WID> struct SP;
template<> struct SP<1>  { static constexpr int SI = 0; static constexpr float INVS2 = 16.0f; };
template<> struct SP<3>  { static constexpr int SI = 1; static constexpr float INVS2 = 1.77777778f; };
template<> struct SP<8>  { static constexpr int SI = 2; static constexpr float INVS2 = 0.326530612f; };
template<> struct SP<18> { static constexpr int SI = 3; static constexpr float INVS2 = 0.0711111111f; };

// STAGE 1: H-morph of x (virtual H edge-pad, only Wn real columns), c=dilate/o=erode, taps k
// STAGE 2: W-morph, clamped col index emulates W edge-pad, c=dilate/o=erode, taps k
// STAGE 3: H-morph (VALID), c=erode/o=dilate, taps k*c
// STAGE 4: W-morph (VALID), c=erode/o=dilate, taps k*c, alpha-blend, final store
template<int WID, int STAGE, int BH>
__global__ __launch_bounds__(256)
void morph(const __half2* __restrict__ in, __half2* __restrict__ out,
           const float* __restrict__ x,
           const float* __restrict__ coef, const float* __restrict__ cmul,
           const float* __restrict__ alpha, float* __restrict__ outF)
{
    constexpr int  L      = 2 * WID + 1;
    constexpr int  P      = 2 * WID;
    constexpr bool SECOND = (STAGE >= 3);
    constexpr int NM = (STAGE == 1) ? (Hn + P) : (STAGE == 2) ? (Wn + P)
                     : (STAGE == 3) ? Hn : Wn;                 // outputs along morph axis
    constexpr int NL = (STAGE == 1) ? Wn : (STAGE == 2) ? (Hn + P)
                     : (STAGE == 3) ? (Wn + P) : Hn;           // independent lines

    const int lane = threadIdx.x & 31;
    const int warp = threadIdx.x >> 5;
    const int b    = blockIdx.z;
    const int line = blockIdx.y * 8 + warp;
    const int a0   = blockIdx.x * BH;
    if (line >= NL) return;

    float a = coef[lane] * SP<WID>::INVS2;
    if (SECOND) a *= cmul[lane];

    const float PINF = __int_as_float(0x7f800000);
    float vc[BH], vo[BH];
#pragma unroll
    for (int p = 0; p < BH; ++p) {
        vc[p] = SECOND ?  PINF : -PINF;
        vo[p] = SECOND ? -PINF :  PINF;
    }

    auto taps1 = [&](float v, int m) {
#pragma unroll
        for (int p = 0; p < BH; ++p) {
            int j = m - p;
            if (j < 0 || j >= L) continue;
            float dj2 = (float)((j - WID) * (j - WID));
            vc[p] = fmaxf(vc[p], fmaf(-dj2, a, v));
            vo[p] = fminf(vo[p], fmaf( dj2, a, v));
        }
    };
    auto taps = [&](float xc, float xo, int m) {
#pragma unroll
        for (int p = 0; p < BH; ++p) {
            int j = m - p;
            if (j < 0 || j >= L) continue;
            float dj2 = (float)((j - WID) * (j - WID));
            if (!SECOND) {
                vc[p] = fmaxf(vc[p], fmaf(-dj2, a, xc));
                vo[p] = fminf(vo[p], fmaf( dj2, a, xo));
            } else {
                vc[p] = fminf(vc[p], fmaf( dj2, a, xc));
                vo[p] = fmaxf(vo[p], fmaf(-dj2, a, xo));
            }
        }
    };

    if constexpr (STAGE == 1) {
        // x[B,H,W,S,C]; line = real W column
        const float* px = x + ((b * Hn * Wn + line) * Sn + SP<WID>::SI) * Cn + lane;
        constexpr int RS = Wn * Sn * Cn;
        const bool interior = (a0 >= P) && (a0 + BH + L - 2 - P <= Hn - 1);
        if (interior) {
            const float* p0 = px + (a0 - P) * RS;
#pragma unroll
            for (int m = 0; m < BH + L - 1; ++m) taps1(__ldg(p0 + m * RS), m);
        } else {
#pragma unroll
            for (int m = 0; m < BH + L - 1; ++m) {
                int xh = min(max(a0 + m - P, 0), Hn - 1);
                taps1(__ldg(px + xh * RS), m);
            }
        }
    } else if constexpr (STAGE == 2) {
        // in: rows Hn+P, cols Wn (deduped); emulate W edge-pad by clamping col
        const __half2* pr = in + (b * (Hn + P) + line) * (Wn * Cn) + lane;
        const bool interior = (a0 >= P) && (a0 + BH + L - 2 - P <= Wn - 1);
        if (interior) {
            const __half2* p0 = pr + (a0 - P) * Cn;
#pragma unroll
            for (int m = 0; m < BH + L - 1; ++m) {
                float2 f = __half22float2(__ldg(p0 + m * Cn));
                taps(f.x, f.y, m);
            }
        } else {
#pragma unroll
            for (int m = 0; m < BH + L - 1; ++m) {
                int cidx = min(max(a0 + m - P, 0), Wn - 1);
                float2 f = __half22float2(__ldg(pr + cidx * Cn));
                taps(f.x, f.y, m);
            }
        }
    } else if constexpr (STAGE == 3) {
        // in: rows Hn+P, cols Wn+P; VALID along rows
        const __half2* p0 = in + ((b * (Hn + P) + a0) * (Wn + P) + line) * Cn + lane;
        constexpr int MS = (Wn + P) * Cn;
#pragma unroll
        for (int m = 0; m < BH + L - 1; ++m) {
            float2 f = __half22float2(__ldg(p0 + m * MS));
            taps(f.x, f.y, m);
        }
    } else {
        // in: rows Hn, cols Wn+P; VALID along cols
        const __half2* p0 = in + ((b * Hn + line) * (Wn + P) + a0) * Cn + lane;
#pragma unroll
        for (int m = 0; m < BH + L - 1; ++m) {
            float2 f = __half22float2(__ldg(p0 + m * Cn));
            taps(f.x, f.y, m);
        }
    }

    if constexpr (STAGE == 4) {
        float al = alpha[lane];
#pragma unroll
        for (int p = 0; p < BH; ++p) {
            int ow = a0 + p;
            if (ow >= NM) continue;
            float r = fmaf(al, vc[p] - vo[p], vo[p]);
            outF[(((b * Hn + line) * Wn + ow) * Sn + SP<WID>::SI) * Cn + lane] = r;
        }
    } else if constexpr (STAGE == 1) {   // out rows Hn+P, cols Wn
        const int base = ((b * (Hn + P) + a0) * Wn + line) * Cn + lane;
#pragma unroll
        for (int p = 0; p < BH; ++p) {
            int oh = a0 + p;
            if (oh >= NM) continue;
            out[base + p * (Wn * Cn)] = __floats2half2_rn(vc[p], vo[p]);
        }
    } else if constexpr (STAGE == 2) {   // out rows Hn+P, cols Wn+P
        const int base = ((b * (Hn + P) + line) * (Wn + P) + a0) * Cn + lane;
#pragma unroll
        for (int p = 0; p < BH; ++p) {
            int ow = a0 + p;
            if (ow >= NM) continue;
            out[base + p * Cn] = __floats2half2_rn(vc[p], vo[p]);
        }
    } else {                              // stage 3: out rows Hn, cols Wn+P
        const int base = ((b * Hn + a0) * (Wn + P) + line) * Cn + lane;
#pragma unroll
        for (int p = 0; p < BH; ++p) {
            int oh = a0 + p;
            if (oh >= NM) continue;
            out[base + p * ((Wn + P) * Cn)] = __floats2half2_rn(vc[p], vo[p]);
        }
    }
}

static inline int cdiv(int a, int b) { return (a + b - 1) / b; }

template<int WID>
static void run_scale(const float* x, const float* coef, const float* cm,
                      const float* al, float* out, __half2* g1, __half2* g2,
                      cudaStream_t st)
{
    constexpr int BH = 16;
    constexpr int P = 2 * WID;
    morph<WID, 1, BH><<<dim3(cdiv(Hn + P, BH), cdiv(Wn, 8),     Bn), 256, 0, st>>>(
        nullptr, g1, x, coef, cm, al, nullptr);
    morph<WID, 2, BH><<<dim3(cdiv(Wn + P, BH), cdiv(Hn + P, 8), Bn), 256, 0, st>>>(
        g1, g2, nullptr, coef, cm, al, nullptr);
    morph<WID, 3, BH><<<dim3(cdiv(Hn, BH),     cdiv(Wn + P, 8), Bn), 256, 0, st>>>(
        g2, g1, nullptr, coef, cm, al, nullptr);
    morph<WID, 4, BH><<<dim3(cdiv(Wn, BH),     cdiv(Hn, 8),     Bn), 256, 0, st>>>(
        g1, nullptr, nullptr, coef, cm, al, out);
}

extern "C" void kernel_launch(void* const* d_in, const int* in_sizes, int n_in,
                              void* d_out, int out_size)
{
    const float* x    = (const float*)d_in[0];
    const float* coef = (const float*)d_in[1];
    const float* cm   = (const float*)d_in[2];
    const float* al   = (const float*)d_in[3];
    float* out = (float*)d_out;

    __half2 *a1, *a2, *b1, *b2;
    cudaGetSymbolAddress((void**)&a1, g_A1);
    cudaGetSymbolAddress((void**)&a2, g_A2);
    cudaGetSymbolAddress((void**)&b1, g_B1);
    cudaGetSymbolAddress((void**)&b2, g_B2);

    static cudaStream_t sB = nullptr;
    static cudaEvent_t evF = nullptr, evJ = nullptr;
    if (!sB) {
        cudaStreamCreateWithFlags(&sB, cudaStreamNonBlocking);
        cudaEventCreateWithFlags(&evF, cudaEventDisableTiming);
        cudaEventCreateWithFlags(&evJ, cudaEventDisableTiming);
    }

    // Fork: stream B (mem-bound small scales) overlaps stream 0 (alu-bound big scales)
    cudaEventRecord(evF, 0);
    cudaStreamWaitEvent(sB, evF, 0);

    run_scale<3> (x, coef, cm, al, out, b1, b2, sB);
    run_scale<1> (x, coef, cm, al, out, b1, b2, sB);
    run_scale<18>(x, coef, cm, al, out, a1, a2, (cudaStream_t)0);
    run_scale<8> (x, coef, cm, al, out, a1, a2, (cudaStream_t)0);

    // Join
    cudaEventRecord(evJ, sB);
    cudaStreamWaitEvent((cudaStream_t)0, evJ, 0);
}

// round 7
// speedup vs baseline: 2.6074x; 1.5894x over previous
#include <cuda_runtime.h>
#include <cuda_fp16.h>

#define Bn 8
#define Hn 192
#define Wn 192
#define Sn 4
#define Cn 32

// Stream-A scratch (w=18, w=1) / Stream-B scratch (w=8, w=3), half2-packed chains.
__device__ __half2 g_A1[11206656 + 262144];   // w18 s1/s3: 228*192*256
__device__ __half2 g_A2[13307904 + 262144];   // w18 s2: 228*228*256
__device__ __half2 g_B1[10223616 + 262144];   // w8 s1/s3: 208*192*256
__device__ __half2 g_B2[11075584 + 262144];   // w8 s2: 208*208*256

template<int WID> struct SP;
template<> struct SP<1>  { static constexpr int SI = 0; static constexpr float INVS2 = 16.0f; };
template<> struct SP<3>  { static constexpr int SI = 1; static constexpr float INVS2 = 1.77777778f; };
template<> struct SP<8>  { static constexpr int SI = 2; static constexpr float INVS2 = 0.326530612f; };
template<> struct SP<18> { static constexpr int SI = 3; static constexpr float INVS2 = 0.0711111111f; };

// exact fp16 bit pattern for small non-negative integers (n <= 2048), duplicated
// into both halves of a 32-bit word.
struct TapArr { unsigned int v[64]; };
template<int L, int WID>
__host__ __device__ constexpr TapArr mk_taps() {
    TapArr t{};
    for (int j = 0; j < L; ++j) {
        int n = (j - WID) * (j - WID);
        unsigned short h = 0;
        if (n > 0) {
            int hb = 0;
            for (int i = 0; i < 12; ++i) if ((n >> i) & 1) hb = i;
            unsigned short mant = (unsigned short)((((unsigned)(n - (1 << hb))) << 10) >> hb);
            h = (unsigned short)(((15 + hb) << 10) | mant);
        }
        t.v[j] = (unsigned)h | ((unsigned)h << 16);
    }
    return t;
}

// All stages run max-chains on packed half2:
//  s1: in x fp32 -> u=(v,-v);  acc=(vc1, -vo1)           taps -a
//  s2: in (vc1,-vo1) direct;   acc=(vc2, -vo2)           taps -a
//  s3: in (vc2,-vo2), u=-in;   acc=(-vc3, vo3)           taps -a*c
//  s4: in (-vc3,vo3) direct;   acc=(-vc4, vo4) -> blend  taps -a*c
template<int WID, int STAGE, int BH>
__global__ __launch_bounds__(128)
void morph(const __half2* __restrict__ in, __half2* __restrict__ out,
           const float* __restrict__ x,
           const float* __restrict__ coef, const float* __restrict__ cmul,
           const float* __restrict__ alpha, float* __restrict__ outF)
{
    constexpr int  L = 2 * WID + 1;
    constexpr int  P = 2 * WID;
    constexpr int NM = (STAGE == 1) ? (Hn + P) : (STAGE == 2) ? (Wn + P)
                     : (STAGE == 3) ? Hn : Wn;
    constexpr int NL = (STAGE == 1) ? Wn : (STAGE == 2) ? (Hn + P)
                     : (STAGE == 3) ? (Wn + P) : Hn;
    constexpr TapArr TT = mk_taps<L, WID>();

    const int lane = threadIdx.x & 31;
    const int warp = threadIdx.x >> 5;
    const int b    = blockIdx.z;
    const int line = blockIdx.y * 4 + warp;
    const int a0   = blockIdx.x * BH;
    if (line >= NL) return;

    float af = coef[lane] * SP<WID>::INVS2;
    if (STAGE >= 3) af *= cmul[lane];
    const __half2 ah2 = __float2half2_rn(-af);

    const __half2 NINF = __halves2half2(__ushort_as_half(0xFC00), __ushort_as_half(0xFC00));
    __half2 acc[BH];
#pragma unroll
    for (int p = 0; p < BH; ++p) acc[p] = NINF;

    auto tap = [&](__half2 u, int m) {
#pragma unroll
        for (int p = 0; p < BH; ++p) {
            int j = m - p;
            if (j < 0 || j >= L) continue;
            unsigned int tb = TT.v[j];
            __half2 dj = *reinterpret_cast<const __half2*>(&tb);
            acc[p] = __hmax2(acc[p], __hfma2(dj, ah2, u));
        }
    };

    if constexpr (STAGE == 1) {
        const float* px = x + ((b * Hn * Wn + line) * Sn + SP<WID>::SI) * Cn + lane;
        constexpr int RS = Wn * Sn * Cn;
        const bool interior = (a0 >= P) && (a0 + BH + L - 2 - P <= Hn - 1);
        if (interior) {
            const float* p0 = px + (a0 - P) * RS;
#pragma unroll
            for (int m = 0; m < BH + L - 1; ++m) {
                float v = __ldg(p0 + m * RS);
                tap(__floats2half2_rn(v, -v), m);
            }
        } else {
#pragma unroll
            for (int m = 0; m < BH + L - 1; ++m) {
                int xh = min(max(a0 + m - P, 0), Hn - 1);
                float v = __ldg(px + xh * RS);
                tap(__floats2half2_rn(v, -v), m);
            }
        }
    } else if constexpr (STAGE == 2) {
        const __half2* pr = in + (b * (Hn + P) + line) * (Wn * Cn) + lane;
        const bool interior = (a0 >= P) && (a0 + BH + L - 2 - P <= Wn - 1);
        if (interior) {
            const __half2* p0 = pr + (a0 - P) * Cn;
#pragma unroll
            for (int m = 0; m < BH + L - 1; ++m) tap(__ldg(p0 + m * Cn), m);
        } else {
#pragma unroll
            for (int m = 0; m < BH + L - 1; ++m) {
                int cidx = min(max(a0 + m - P, 0), Wn - 1);
                tap(__ldg(pr + cidx * Cn), m);
            }
        }
    } else if constexpr (STAGE == 3) {
        const __half2* p0 = in + ((b * (Hn + P) + a0) * (Wn + P) + line) * Cn + lane;
        constexpr int MS = (Wn + P) * Cn;
#pragma unroll
        for (int m = 0; m < BH + L - 1; ++m) tap(__hneg2(__ldg(p0 + m * MS)), m);
    } else {
        const __half2* p0 = in + ((b * Hn + line) * (Wn + P) + a0) * Cn + lane;
#pragma unroll
        for (int m = 0; m < BH + L - 1; ++m) tap(__ldg(p0 + m * Cn), m);
    }

    if constexpr (STAGE == 4) {
        float al = alpha[lane];
#pragma unroll
        for (int p = 0; p < BH; ++p) {
            float vc = -__low2float(acc[p]);
            float vo =  __high2float(acc[p]);
            float r  = fmaf(al, vc - vo, vo);   // alpha*xc + (1-alpha)*xo
            outF[(((b * Hn + line) * Wn + (a0 + p)) * Sn + SP<WID>::SI) * Cn + lane] = r;
        }
    } else if constexpr (STAGE == 1) {   // rows Hn+P x cols Wn — GUARDED (inexact tile)
        const int base = ((b * (Hn + P) + a0) * Wn + line) * Cn + lane;
#pragma unroll
        for (int p = 0; p < BH; ++p) {
            if (a0 + p >= NM) continue;  // row bleed would corrupt batch b+1
            out[base + p * (Wn * Cn)] = acc[p];
        }
    } else if constexpr (STAGE == 2) {   // rows Hn+P x cols Wn+P — GUARDED (inexact tile)
        const int base = ((b * (Hn + P) + line) * (Wn + P) + a0) * Cn + lane;
#pragma unroll
        for (int p = 0; p < BH; ++p) {
            if (a0 + p >= NM) continue;  // col bleed would corrupt next line
            out[base + p * Cn] = acc[p];
        }
    } else {                              // stage 3: rows Hn (exact 12*16 tiles)
        const int base = ((b * Hn + a0) * (Wn + P) + line) * Cn + lane;
#pragma unroll
        for (int p = 0; p < BH; ++p) out[base + p * ((Wn + P) * Cn)] = acc[p];
    }
}

static inline int cdiv(int a, int b) { return (a + b - 1) / b; }

template<int WID>
static void run_scale(const float* x, const float* coef, const float* cm,
                      const float* al, float* out, __half2* g1, __half2* g2,
                      cudaStream_t st)
{
    constexpr int BH = 16;
    constexpr int P = 2 * WID;
    morph<WID, 1, BH><<<dim3(cdiv(Hn + P, BH), cdiv(Wn, 4),     Bn), 128, 0, st>>>(
        nullptr, g1, x, coef, cm, al, nullptr);
    morph<WID, 2, BH><<<dim3(cdiv(Wn + P, BH), cdiv(Hn + P, 4), Bn), 128, 0, st>>>(
        g1, g2, nullptr, coef, cm, al, nullptr);
    morph<WID, 3, BH><<<dim3(cdiv(Hn, BH),     cdiv(Wn + P, 4), Bn), 128, 0, st>>>(
        g2, g1, nullptr, coef, cm, al, nullptr);
    morph<WID, 4, BH><<<dim3(cdiv(Wn, BH),     cdiv(Hn, 4),     Bn), 128, 0, st>>>(
        g1, nullptr, nullptr, coef, cm, al, out);
}

extern "C" void kernel_launch(void* const* d_in, const int* in_sizes, int n_in,
                              void* d_out, int out_size)
{
    const float* x    = (const float*)d_in[0];
    const float* coef = (const float*)d_in[1];
    const float* cm   = (const float*)d_in[2];
    const float* al   = (const float*)d_in[3];
    float* out = (float*)d_out;

    __half2 *a1, *a2, *b1, *b2;
    cudaGetSymbolAddress((void**)&a1, g_A1);
    cudaGetSymbolAddress((void**)&a2, g_A2);
    cudaGetSymbolAddress((void**)&b1, g_B1);
    cudaGetSymbolAddress((void**)&b2, g_B2);

    static cudaStream_t sB = nullptr;
    static cudaEvent_t evF = nullptr, evJ = nullptr;
    if (!sB) {
        cudaStreamCreateWithFlags(&sB, cudaStreamNonBlocking);
        cudaEventCreateWithFlags(&evF, cudaEventDisableTiming);
        cudaEventCreateWithFlags(&evJ, cudaEventDisableTiming);
    }

    cudaEventRecord(evF, 0);
    cudaStreamWaitEvent(sB, evF, 0);

    // A: w18 + w1 ; B: w8 + w3  (balanced tap-pair totals)
    run_scale<8> (x, coef, cm, al, out, b1, b2, sB);
    run_scale<3> (x, coef, cm, al, out, b1, b2, sB);
    run_scale<18>(x, coef, cm, al, out, a1, a2, (cudaStream_t)0);
    run_scale<1> (x, coef, cm, al, out, a1, a2, (cudaStream_t)0);

    cudaEventRecord(evJ, sB);
    cudaStreamWaitEvent((cudaStream_t)0, evJ, 0);
}

// round 8
// speedup vs baseline: 2.6354x; 1.0107x over previous
#include <cuda_runtime.h>
#include <cuda_fp16.h>

#define Bn 8
#define Hn 192
#define Wn 192
#define Sn 4
#define Cn 32

// Stream-A scratch (w=18, w=1) / Stream-B scratch (w=8, w=3), half2-packed chains.
__device__ __half2 g_A1[11206656 + 262144];   // w18 s1/s3: 228*192*256
__device__ __half2 g_A2[13307904 + 262144];   // w18 s2: 228*228*256
__device__ __half2 g_B1[10223616 + 262144];   // w8 s1/s3: 208*192*256
__device__ __half2 g_B2[11075584 + 262144];   // w8 s2: 208*208*256

template<int WID> struct SP;
template<> struct SP<1>  { static constexpr int SI = 0; static constexpr float INVS2 = 16.0f; };
template<> struct SP<3>  { static constexpr int SI = 1; static constexpr float INVS2 = 1.77777778f; };
template<> struct SP<8>  { static constexpr int SI = 2; static constexpr float INVS2 = 0.326530612f; };
template<> struct SP<18> { static constexpr int SI = 3; static constexpr float INVS2 = 0.0711111111f; };

// exact fp16 bit pattern for small non-negative integers (n <= 2048), duplicated.
struct TapArr { unsigned int v[64]; };
template<int L, int WID>
__host__ __device__ constexpr TapArr mk_taps() {
    TapArr t{};
    for (int j = 0; j < L; ++j) {
        int n = (j - WID) * (j - WID);
        unsigned short h = 0;
        if (n > 0) {
            int hb = 0;
            for (int i = 0; i < 12; ++i) if ((n >> i) & 1) hb = i;
            unsigned short mant = (unsigned short)((((unsigned)(n - (1 << hb))) << 10) >> hb);
            h = (unsigned short)(((15 + hb) << 10) | mant);
        }
        t.v[j] = (unsigned)h | ((unsigned)h << 16);
    }
    return t;
}

// All stages run max-chains on packed half2:
//  s1: in x fp32 -> u=(v,-v);  acc=(vc1, -vo1)           taps -a
//  s2: in (vc1,-vo1) direct;   acc=(vc2, -vo2)           taps -a
//  s3: in (vc2,-vo2), u=-in;   acc=(-vc3, vo3)           taps -a*c
//  s4: in (-vc3,vo3) direct;   acc=(-vc4, vo4) -> blend  taps -a*c
template<int WID, int STAGE, int BH>
__global__ __launch_bounds__(128)
void morph(const __half2* __restrict__ in, __half2* __restrict__ out,
           const float* __restrict__ x,
           const float* __restrict__ coef, const float* __restrict__ cmul,
           const float* __restrict__ alpha, float* __restrict__ outF)
{
    constexpr int  L = 2 * WID + 1;
    constexpr int  P = 2 * WID;
    constexpr int  M = BH + L - 1;     // inputs per block along morph axis
    constexpr int  CH = 16;            // prefetch chunk (MLP)
    constexpr int NM = (STAGE == 1) ? (Hn + P) : (STAGE == 2) ? (Wn + P)
                     : (STAGE == 3) ? Hn : Wn;
    constexpr int NL = (STAGE == 1) ? Wn : (STAGE == 2) ? (Hn + P)
                     : (STAGE == 3) ? (Wn + P) : Hn;
    constexpr TapArr TT = mk_taps<L, WID>();

    const int lane = threadIdx.x & 31;
    const int warp = threadIdx.x >> 5;
    const int b    = blockIdx.z;
    const int line = blockIdx.y * 4 + warp;
    const int a0   = blockIdx.x * BH;
    if (line >= NL) return;

    float af = coef[lane] * SP<WID>::INVS2;
    if (STAGE >= 3) af *= cmul[lane];
    const __half2 ah2 = __float2half2_rn(-af);

    const __half2 NINF = __halves2half2(__ushort_as_half(0xFC00), __ushort_as_half(0xFC00));
    __half2 acc[BH];
#pragma unroll
    for (int p = 0; p < BH; ++p) acc[p] = NINF;

    auto tap = [&](__half2 u, int m) {
#pragma unroll
        for (int p = 0; p < BH; ++p) {
            int j = m - p;
            if (j < 0 || j >= L) continue;
            unsigned int tb = TT.v[j];
            __half2 dj = *reinterpret_cast<const __half2*>(&tb);
            acc[p] = __hmax2(acc[p], __hfma2(dj, ah2, u));
        }
    };

    if constexpr (STAGE == 1) {
        const float* px = x + ((b * Hn * Wn + line) * Sn + SP<WID>::SI) * Cn + lane;
        constexpr int RS = Wn * Sn * Cn;
        const bool interior = (a0 >= P) && (a0 + M - 1 - P <= Hn - 1);
        if (interior) {
            const float* p0 = px + (a0 - P) * RS;
#pragma unroll
            for (int m0 = 0; m0 < M; m0 += CH) {
                float u[CH];
#pragma unroll
                for (int q = 0; q < CH; ++q)
                    if (m0 + q < M) u[q] = __ldg(p0 + (m0 + q) * RS);
#pragma unroll
                for (int q = 0; q < CH; ++q)
                    if (m0 + q < M) tap(__floats2half2_rn(u[q], -u[q]), m0 + q);
            }
        } else {
#pragma unroll
            for (int m0 = 0; m0 < M; m0 += CH) {
                float u[CH];
#pragma unroll
                for (int q = 0; q < CH; ++q)
                    if (m0 + q < M) {
                        int xh = min(max(a0 + m0 + q - P, 0), Hn - 1);
                        u[q] = __ldg(px + xh * RS);
                    }
#pragma unroll
                for (int q = 0; q < CH; ++q)
                    if (m0 + q < M) tap(__floats2half2_rn(u[q], -u[q]), m0 + q);
            }
        }
    } else if constexpr (STAGE == 2) {
        const __half2* pr = in + (b * (Hn + P) + line) * (Wn * Cn) + lane;
        const bool interior = (a0 >= P) && (a0 + M - 1 - P <= Wn - 1);
        if (interior) {
            const __half2* p0 = pr + (a0 - P) * Cn;
#pragma unroll
            for (int m0 = 0; m0 < M; m0 += CH) {
                __half2 u[CH];
#pragma unroll
                for (int q = 0; q < CH; ++q)
                    if (m0 + q < M) u[q] = __ldg(p0 + (m0 + q) * Cn);
#pragma unroll
                for (int q = 0; q < CH; ++q)
                    if (m0 + q < M) tap(u[q], m0 + q);
            }
        } else {
#pragma unroll
            for (int m0 = 0; m0 < M; m0 += CH) {
                __half2 u[CH];
#pragma unroll
                for (int q = 0; q < CH; ++q)
                    if (m0 + q < M) {
                        int cidx = min(max(a0 + m0 + q - P, 0), Wn - 1);
                        u[q] = __ldg(pr + cidx * Cn);
                    }
#pragma unroll
                for (int q = 0; q < CH; ++q)
                    if (m0 + q < M) tap(u[q], m0 + q);
            }
        }
    } else if constexpr (STAGE == 3) {
        const __half2* p0 = in + ((b * (Hn + P) + a0) * (Wn + P) + line) * Cn + lane;
        constexpr int MS = (Wn + P) * Cn;
#pragma unroll
        for (int m0 = 0; m0 < M; m0 += CH) {
            __half2 u[CH];
#pragma unroll
            for (int q = 0; q < CH; ++q)
                if (m0 + q < M) u[q] = __ldg(p0 + (m0 + q) * MS);
#pragma unroll
            for (int q = 0; q < CH; ++q)
                if (m0 + q < M) tap(__hneg2(u[q]), m0 + q);
        }
    } else {
        const __half2* p0 = in + ((b * Hn + line) * (Wn + P) + a0) * Cn + lane;
#pragma unroll
        for (int m0 = 0; m0 < M; m0 += CH) {
            __half2 u[CH];
#pragma unroll
            for (int q = 0; q < CH; ++q)
                if (m0 + q < M) u[q] = __ldg(p0 + (m0 + q) * Cn);
#pragma unroll
            for (int q = 0; q < CH; ++q)
                if (m0 + q < M) tap(u[q], m0 + q);
        }
    }

    if constexpr (STAGE == 4) {
        float al = alpha[lane];
#pragma unroll
        for (int p = 0; p < BH; ++p) {
            float vc = -__low2float(acc[p]);
            float vo =  __high2float(acc[p]);
            float r  = fmaf(al, vc - vo, vo);   // alpha*xc + (1-alpha)*xo
            outF[(((b * Hn + line) * Wn + (a0 + p)) * Sn + SP<WID>::SI) * Cn + lane] = r;
        }
    } else if constexpr (STAGE == 1) {   // rows Hn+P x cols Wn — GUARDED
        const int base = ((b * (Hn + P) + a0) * Wn + line) * Cn + lane;
#pragma unroll
        for (int p = 0; p < BH; ++p) {
            if (a0 + p >= NM) continue;
            out[base + p * (Wn * Cn)] = acc[p];
        }
    } else if constexpr (STAGE == 2) {   // rows Hn+P x cols Wn+P — GUARDED
        const int base = ((b * (Hn + P) + line) * (Wn + P) + a0) * Cn + lane;
#pragma unroll
        for (int p = 0; p < BH; ++p) {
            if (a0 + p >= NM) continue;
            out[base + p * Cn] = acc[p];
        }
    } else {                              // stage 3: rows Hn (exact tiles)
        const int base = ((b * Hn + a0) * (Wn + P) + line) * Cn + lane;
#pragma unroll
        for (int p = 0; p < BH; ++p) out[base + p * ((Wn + P) * Cn)] = acc[p];
    }
}

static inline int cdiv(int a, int b) { return (a + b - 1) / b; }

template<int WID>
static void run_scale(const float* x, const float* coef, const float* cm,
                      const float* al, float* out, __half2* g1, __half2* g2,
                      cudaStream_t st)
{
    constexpr int BH = 16;
    constexpr int P = 2 * WID;
    morph<WID, 1, BH><<<dim3(cdiv(Hn + P, BH), cdiv(Wn, 4),     Bn), 128, 0, st>>>(
        nullptr, g1, x, coef, cm, al, nullptr);
    morph<WID, 2, BH><<<dim3(cdiv(Wn + P, BH), cdiv(Hn + P, 4), Bn), 128, 0, st>>>(
        g1, g2, nullptr, coef, cm, al, nullptr);
    morph<WID, 3, BH><<<dim3(cdiv(Hn, BH),     cdiv(Wn + P, 4), Bn), 128, 0, st>>>(
        g2, g1, nullptr, coef, cm, al, nullptr);
    morph<WID, 4, BH><<<dim3(cdiv(Wn, BH),     cdiv(Hn, 4),     Bn), 128, 0, st>>>(
        g1, nullptr, nullptr, coef, cm, al, out);
}

extern "C" void kernel_launch(void* const* d_in, const int* in_sizes, int n_in,
                              void* d_out, int out_size)
{
    const float* x    = (const float*)d_in[0];
    const float* coef = (const float*)d_in[1];
    const float* cm   = (const float*)d_in[2];
    const float* al   = (const float*)d_in[3];
    float* out = (float*)d_out;

    __half2 *a1, *a2, *b1, *b2;
    cudaGetSymbolAddress((void**)&a1, g_A1);
    cudaGetSymbolAddress((void**)&a2, g_A2);
    cudaGetSymbolAddress((void**)&b1, g_B1);
    cudaGetSymbolAddress((void**)&b2, g_B2);

    static cudaStream_t sB = nullptr;
    static cudaEvent_t evF = nullptr, evJ = nullptr;
    if (!sB) {
        cudaStreamCreateWithFlags(&sB, cudaStreamNonBlocking);
        cudaEventCreateWithFlags(&evF, cudaEventDisableTiming);
        cudaEventCreateWithFlags(&evJ, cudaEventDisableTiming);
    }

    cudaEventRecord(evF, 0);
    cudaStreamWaitEvent(sB, evF, 0);

    // A: w18 + w1 ; B: w8 + w3  (balanced tap-pair totals)
    run_scale<8> (x, coef, cm, al, out, b1, b2, sB);
    run_scale<3> (x, coef, cm, al, out, b1, b2, sB);
    run_scale<18>(x, coef, cm, al, out, a1, a2, (cudaStream_t)0);
    run_scale<1> (x, coef, cm, al, out, a1, a2, (cudaStream_t)0);

    cudaEventRecord(evJ, sB);
    cudaStreamWaitEvent((cudaStream_t)0, evJ, 0);
}